// round 7
// baseline (speedup 1.0000x reference)
#include <cuda_runtime.h>
#include <math.h>
#include <stdint.h>

#define HIDDEN   1280
#define NH       16
#define HD       80
#define S_TOT    16384
#define WIN      64
#define NWIN     256
#define ROT      40
#define QKV_N    (3*HIDDEN)

// Scratch (allocation-free rule: __device__ globals)
__device__ float g_qkv[(size_t)S_TOT * QKV_N];    // [S, 3*1280]
__device__ float g_attn[(size_t)S_TOT * HIDDEN];  // [S, 1280]

// ----------------------------------------------------------------------------
// Helpers: tf32 split + mma.m16n8k8 + cp.async
// ----------------------------------------------------------------------------
__device__ __forceinline__ uint32_t f32_to_tf32(float x) {
    uint32_t r;
    asm("cvt.rna.tf32.f32 %0, %1;" : "=r"(r) : "f"(x));
    return r;
}
__device__ __forceinline__ void split_tf32(float x, uint32_t& hi, uint32_t& lo) {
    hi = f32_to_tf32(x);
    float r = x - __uint_as_float(hi);   // exact (Dekker residual)
    lo = f32_to_tf32(r);
}
__device__ __forceinline__ void mma_tf32(float c[4], const uint32_t a[4],
                                         const uint32_t b[2]) {
    asm volatile(
        "mma.sync.aligned.m16n8k8.row.col.f32.tf32.tf32.f32 "
        "{%0,%1,%2,%3}, {%4,%5,%6,%7}, {%8,%9}, {%0,%1,%2,%3};"
        : "+f"(c[0]), "+f"(c[1]), "+f"(c[2]), "+f"(c[3])
        : "r"(a[0]), "r"(a[1]), "r"(a[2]), "r"(a[3]), "r"(b[0]), "r"(b[1]));
}
// .cg = L2-only: staged tiles have zero L1 reuse (consumed once from smem).
__device__ __forceinline__ void cp_async16(uint32_t smem_dst, const void* gsrc) {
    asm volatile("cp.async.cg.shared.global [%0], [%1], 16;\n"
                 :: "r"(smem_dst), "l"(gsrc));
}
__device__ __forceinline__ void cp_async_commit() {
    asm volatile("cp.async.commit_group;\n" ::: "memory");
}
__device__ __forceinline__ void cp_async_wait0() {
    asm volatile("cp.async.wait_group 0;\n" ::: "memory");
}

// ----------------------------------------------------------------------------
// Tensor-core GEMM: C[m,n] = sum_k A[m,k]*B[n,k] + bias[n]  (3xTF32 split)
// BM=BN=128, BK=16, 256 threads = 8 warps in 4(m) x 2(n); warp tile 32x64.
// Smem row-major, stride 20 (fragment reads hit all 32 banks: (20g+t) mod 32).
// cp.async.cg double-buffered staging; one barrier per K-tile.
// MMA schedule term-major: 16 independent fragments between accumulator reuses.
// M,N,K divisible by tiles (16384, 3840/1280, 1280). No bounds checks.
// ----------------------------------------------------------------------------
#define SPAD 20
__global__ __launch_bounds__(256)
void gemm_tc_nt_bias(const float* __restrict__ A, const float* __restrict__ B,
                     const float* __restrict__ bias, float* __restrict__ C,
                     int M, int N, int K) {
    __shared__ float As[2][128][SPAD];
    __shared__ float Bs[2][128][SPAD];

    const int tid  = threadIdx.x;
    const int warp = tid >> 5;
    const int lane = tid & 31;
    const int g    = lane >> 2;    // 0..7
    const int t    = lane & 3;     // 0..3
    const int wm   = warp & 3;     // m offset wm*32
    const int wn   = warp >> 2;    // n offset wn*64

    const float* Ab = A + (size_t)blockIdx.y * 128 * K;
    const float* Bb = B + (size_t)blockIdx.x * 128 * K;

    // Staging slots: 2 x 16B per thread for each of A,B per K-tile.
    const int row0 = tid >> 2,         k40 = (tid & 3) << 2;
    const int row1 = (tid + 256) >> 2; // same k40 for second slot

    const uint32_t sA0 = (uint32_t)__cvta_generic_to_shared(&As[0][row0][k40]);
    const uint32_t sA1 = (uint32_t)__cvta_generic_to_shared(&As[0][row1][k40]);
    const uint32_t sB0 = (uint32_t)__cvta_generic_to_shared(&Bs[0][row0][k40]);
    const uint32_t sB1 = (uint32_t)__cvta_generic_to_shared(&Bs[0][row1][k40]);
    const uint32_t bufStride = (uint32_t)(128 * SPAD * sizeof(float)); // buf1-buf0

    // Prologue: tile 0 -> buffer 0 via cp.async.
    cp_async16(sA0, Ab + (size_t)row0 * K + k40);
    cp_async16(sA1, Ab + (size_t)row1 * K + k40);
    cp_async16(sB0, Bb + (size_t)row0 * K + k40);
    cp_async16(sB1, Bb + (size_t)row1 * K + k40);
    cp_async_commit();
    cp_async_wait0();
    __syncthreads();

    float acc[2][8][4];
#pragma unroll
    for (int mt = 0; mt < 2; mt++)
#pragma unroll
        for (int nt = 0; nt < 8; nt++)
#pragma unroll
            for (int i = 0; i < 4; i++) acc[mt][nt][i] = 0.f;

    const int nk = K / 16;
    for (int tt = 0; tt < nk; tt++) {
        const int buf = tt & 1;

        // Kick off async copy of tile t+1 into the alternate buffer.
        if (tt + 1 < nk) {
            const int k0 = (tt + 1) * 16;
            const uint32_t off = (buf ^ 1) ? bufStride : 0u;
            cp_async16(sA0 + off, Ab + (size_t)row0 * K + k0 + k40);
            cp_async16(sA1 + off, Ab + (size_t)row1 * K + k0 + k40);
            cp_async16(sB0 + off, Bb + (size_t)row0 * K + k0 + k40);
            cp_async16(sB1 + off, Bb + (size_t)row1 * K + k0 + k40);
            cp_async_commit();
        }

#pragma unroll
        for (int s = 0; s < 2; s++) {           // two k8 steps per K-tile
            const int kb = s * 8;

            // A fragments: a0=(g,t) a1=(g+8,t) a2=(g,t+4) a3=(g+8,t+4)
            uint32_t ahi[2][4], alo[2][4];
#pragma unroll
            for (int mt = 0; mt < 2; mt++) {
                const int rm = wm * 32 + mt * 16;
                float a0 = As[buf][rm + g][kb + t];
                float a1 = As[buf][rm + g + 8][kb + t];
                float a2 = As[buf][rm + g][kb + t + 4];
                float a3 = As[buf][rm + g + 8][kb + t + 4];
                split_tf32(a0, ahi[mt][0], alo[mt][0]);
                split_tf32(a1, ahi[mt][1], alo[mt][1]);
                split_tf32(a2, ahi[mt][2], alo[mt][2]);
                split_tf32(a3, ahi[mt][3], alo[mt][3]);
            }

            // B fragments (col-major B = our [n][k]): b0=(k=t,n=g) b1=(k=t+4,n=g)
            uint32_t bhi[8][2], blo[8][2];
#pragma unroll
            for (int nt = 0; nt < 8; nt++) {
                const int nb = wn * 64 + nt * 8;
                float b0 = Bs[buf][nb + g][kb + t];
                float b1 = Bs[buf][nb + g][kb + t + 4];
                split_tf32(b0, bhi[nt][0], blo[nt][0]);
                split_tf32(b1, bhi[nt][1], blo[nt][1]);
            }

            // Term-major schedule: consecutive MMAs never share an accumulator.
#pragma unroll
            for (int nt = 0; nt < 8; nt++)
#pragma unroll
                for (int mt = 0; mt < 2; mt++)
                    mma_tf32(acc[mt][nt], ahi[mt], bhi[nt]);
#pragma unroll
            for (int nt = 0; nt < 8; nt++)
#pragma unroll
                for (int mt = 0; mt < 2; mt++)
                    mma_tf32(acc[mt][nt], alo[mt], bhi[nt]);
#pragma unroll
            for (int nt = 0; nt < 8; nt++)
#pragma unroll
                for (int mt = 0; mt < 2; mt++)
                    mma_tf32(acc[mt][nt], ahi[mt], blo[nt]);
        }

        if (tt + 1 < nk) {
            cp_async_wait0();
            __syncthreads();
        }
    }

    // Epilogue: bias + store. c0:(g,2t) c1:(g,2t+1) c2:(g+8,2t) c3:(g+8,2t+1)
    const int rbase = blockIdx.y * 128 + wm * 32;
    const int cbase = blockIdx.x * 128 + wn * 64;
#pragma unroll
    for (int nt = 0; nt < 8; nt++) {
        const int cb = cbase + nt * 8 + 2 * t;
        const float2 bb = *(const float2*)&bias[cb];
#pragma unroll
        for (int mt = 0; mt < 2; mt++) {
            const int r0 = rbase + mt * 16 + g;
            float2 v0 = make_float2(acc[mt][nt][0] + bb.x, acc[mt][nt][1] + bb.y);
            float2 v1 = make_float2(acc[mt][nt][2] + bb.x, acc[mt][nt][3] + bb.y);
            *(float2*)(C + (size_t)r0 * N + cb)       = v0;
            *(float2*)(C + (size_t)(r0 + 8) * N + cb) = v1;
        }
    }
}

// ----------------------------------------------------------------------------
// Windowed attention: one CTA per (window, head).
// RoPE applied to q,k while loading into smem. 64x64 scores, softmax, PV.
// ----------------------------------------------------------------------------
#define QK_STRIDE (HD + 1)    // 81
#define P_STRIDE  (WIN + 1)   // 65
#define SM_Q 0
#define SM_K (WIN * QK_STRIDE)
#define SM_V (2 * WIN * QK_STRIDE)
#define SM_P (3 * WIN * QK_STRIDE)
#define ATTN_SMEM_FLOATS (3 * WIN * QK_STRIDE + WIN * P_STRIDE)

__global__ __launch_bounds__(256)
void attn_win(const float* __restrict__ cosT, const float* __restrict__ sinT) {
    extern __shared__ float sm[];
    float* sq = sm + SM_Q;
    float* sk = sm + SM_K;
    float* sv = sm + SM_V;
    float* sp = sm + SM_P;

    const int w   = blockIdx.x;
    const int h   = blockIdx.y;
    const int tid = threadIdx.x;

    const float* base = g_qkv + (size_t)w * WIN * QKV_N + h * HD;

    for (int idx = tid; idx < WIN * ROT; idx += 256) {
        int r = idx / ROT, j = idx - r * ROT;
        int t = w * WIN + r;
        float c = cosT[t * ROT + j];
        float s = sinT[t * ROT + j];
        const float* qp = base + (size_t)r * QKV_N;
        float q1 = qp[j], q2 = qp[j + ROT];
        sq[r * QK_STRIDE + j]       = q1 * c - q2 * s;
        sq[r * QK_STRIDE + j + ROT] = q2 * c + q1 * s;
        float k1 = qp[HIDDEN + j], k2 = qp[HIDDEN + j + ROT];
        sk[r * QK_STRIDE + j]       = k1 * c - k2 * s;
        sk[r * QK_STRIDE + j + ROT] = k2 * c + k1 * s;
    }
    for (int idx = tid; idx < WIN * HD; idx += 256) {
        int r = idx / HD, d = idx - r * HD;
        sv[r * QK_STRIDE + d] = base[(size_t)r * QKV_N + 2 * HIDDEN + d];
    }
    __syncthreads();

    {
        const int tx = tid & 15, ty = tid >> 4;
        float accs[4][4];
#pragma unroll
        for (int i = 0; i < 4; i++)
#pragma unroll
            for (int j = 0; j < 4; j++) accs[i][j] = 0.f;

        const float* qrow = sq + (ty * 4) * QK_STRIDE;
        const float* krow = sk + (tx * 4) * QK_STRIDE;
#pragma unroll 8
        for (int d = 0; d < HD; d++) {
            float qa[4], kb[4];
#pragma unroll
            for (int i = 0; i < 4; i++) qa[i] = qrow[i * QK_STRIDE + d];
#pragma unroll
            for (int j = 0; j < 4; j++) kb[j] = krow[j * QK_STRIDE + d];
#pragma unroll
            for (int i = 0; i < 4; i++)
#pragma unroll
                for (int j = 0; j < 4; j++)
                    accs[i][j] += qa[i] * kb[j];
        }
        const float scale = 0.11180339887498949f;   // 1/sqrt(80)
#pragma unroll
        for (int i = 0; i < 4; i++)
#pragma unroll
            for (int j = 0; j < 4; j++)
                sp[(ty * 4 + i) * P_STRIDE + tx * 4 + j] = accs[i][j] * scale;
    }
    __syncthreads();

    if (tid < WIN) {
        float* row = sp + tid * P_STRIDE;
        float m = row[0];
#pragma unroll 8
        for (int c = 1; c < WIN; c++) m = fmaxf(m, row[c]);
        float sum = 0.f;
#pragma unroll 8
        for (int c = 0; c < WIN; c++) {
            float e = __expf(row[c] - m);
            row[c] = e;
            sum += e;
        }
        float inv = 1.f / sum;
#pragma unroll 8
        for (int c = 0; c < WIN; c++) row[c] *= inv;
    }
    __syncthreads();

    {
        const int tx = tid & 15, ty = tid >> 4;
        float acco[4][5];
#pragma unroll
        for (int i = 0; i < 4; i++)
#pragma unroll
            for (int j = 0; j < 5; j++) acco[i][j] = 0.f;

#pragma unroll 4
        for (int c = 0; c < WIN; c++) {
            float pa[4], vb[5];
#pragma unroll
            for (int i = 0; i < 4; i++) pa[i] = sp[(ty * 4 + i) * P_STRIDE + c];
#pragma unroll
            for (int j = 0; j < 5; j++) vb[j] = sv[c * QK_STRIDE + tx * 5 + j];
#pragma unroll
            for (int i = 0; i < 4; i++)
#pragma unroll
                for (int j = 0; j < 5; j++)
                    acco[i][j] += pa[i] * vb[j];
        }
        float* outp = g_attn + (size_t)(w * WIN) * HIDDEN + h * HD;
#pragma unroll
        for (int i = 0; i < 4; i++)
#pragma unroll
            for (int j = 0; j < 5; j++)
                outp[(size_t)(ty * 4 + i) * HIDDEN + tx * 5 + j] = acco[i][j];
    }
}

// ----------------------------------------------------------------------------
// Launch: QKV GEMM -> windowed attention (RoPE fused) -> proj GEMM
// ----------------------------------------------------------------------------
extern "C" void kernel_launch(void* const* d_in, const int* in_sizes, int n_in,
                              void* d_out, int out_size) {
    const float* x      = (const float*)d_in[0];
    const float* cosT   = (const float*)d_in[1];
    const float* sinT   = (const float*)d_in[2];
    const float* qkv_w  = (const float*)d_in[3];
    const float* qkv_b  = (const float*)d_in[4];
    const float* proj_w = (const float*)d_in[5];
    const float* proj_b = (const float*)d_in[6];
    float* out = (float*)d_out;

    static float* qkv  = nullptr;
    static float* attn = nullptr;
    static bool   init = false;
    if (!init) {
        cudaGetSymbolAddress((void**)&qkv,  g_qkv);
        cudaGetSymbolAddress((void**)&attn, g_attn);
        cudaFuncSetAttribute(attn_win,
                             cudaFuncAttributeMaxDynamicSharedMemorySize,
                             (int)(ATTN_SMEM_FLOATS * sizeof(float)));
        init = true;
    }

    dim3 blk(256);

    dim3 g1(QKV_N / 128, S_TOT / 128);
    gemm_tc_nt_bias<<<g1, blk>>>(x, qkv_w, qkv_b, qkv, S_TOT, QKV_N, HIDDEN);

    attn_win<<<dim3(NWIN, NH), blk, ATTN_SMEM_FLOATS * sizeof(float)>>>(cosT, sinT);

    dim3 g2(HIDDEN / 128, S_TOT / 128);
    gemm_tc_nt_bias<<<g2, blk>>>(attn, proj_w, proj_b, out, S_TOT, HIDDEN, HIDDEN);
}

// round 16
// speedup vs baseline: 1.1485x; 1.1485x over previous
#include <cuda_runtime.h>
#include <math.h>
#include <stdint.h>

#define HIDDEN   1280
#define NH       16
#define HD       80
#define S_TOT    16384
#define WIN      64
#define NWIN     256
#define ROT      40
#define QKV_N    (3*HIDDEN)

// Scratch (allocation-free rule: __device__ globals)
__device__ float g_qkv[(size_t)S_TOT * QKV_N];    // [S, 3*1280]
__device__ float g_attn[(size_t)S_TOT * HIDDEN];  // [S, 1280]

// ----------------------------------------------------------------------------
// Helpers: tf32 split + mma.m16n8k8
// ----------------------------------------------------------------------------
__device__ __forceinline__ uint32_t f32_to_tf32(float x) {
    uint32_t r;
    asm("cvt.rna.tf32.f32 %0, %1;" : "=r"(r) : "f"(x));
    return r;
}
__device__ __forceinline__ void split_tf32(float x, uint32_t& hi, uint32_t& lo) {
    hi = f32_to_tf32(x);
    float r = x - __uint_as_float(hi);   // exact (Dekker residual)
    lo = f32_to_tf32(r);
}
__device__ __forceinline__ void mma_tf32(float c[4], const uint32_t a[4],
                                         const uint32_t b[2]) {
    asm volatile(
        "mma.sync.aligned.m16n8k8.row.col.f32.tf32.tf32.f32 "
        "{%0,%1,%2,%3}, {%4,%5,%6,%7}, {%8,%9}, {%0,%1,%2,%3};"
        : "+f"(c[0]), "+f"(c[1]), "+f"(c[2]), "+f"(c[3])
        : "r"(a[0]), "r"(a[1]), "r"(a[2]), "r"(a[3]), "r"(b[0]), "r"(b[1]));
}
// Split a staged float4 and store hi/lo quads to smem (16B-aligned).
__device__ __forceinline__ void split_store4(float4 v, float* H, float* L, int off) {
    uint32_t h0, l0, h1, l1, h2, l2, h3, l3;
    split_tf32(v.x, h0, l0); split_tf32(v.y, h1, l1);
    split_tf32(v.z, h2, l2); split_tf32(v.w, h3, l3);
    *(float4*)(H + off) = make_float4(__uint_as_float(h0), __uint_as_float(h1),
                                      __uint_as_float(h2), __uint_as_float(h3));
    *(float4*)(L + off) = make_float4(__uint_as_float(l0), __uint_as_float(l1),
                                      __uint_as_float(l2), __uint_as_float(l3));
}

// ----------------------------------------------------------------------------
// Tensor-core GEMM: C[m,n] = sum_k A[m,k]*B[n,k] + bias[n]  (3xTF32 split)
// BM=BN=128, BK=16, 256 threads = 8 warps in 4(m) x 2(n); warp tile 32x64.
// PRE-SPLIT smem: staging splits each element once (LDG->split->STS hi/lo);
// the MMA loop is pure LDS+HMMA (no cvt/sub on the critical path).
// Smem stride 20: fragment reads hit all 32 banks ((20g+t) mod 32 distinct).
// Term-ordered fragment loads (hh -> lh -> hl) keep peak frag regs modest.
// M,N,K divisible by tiles (16384, 3840/1280, 1280). No bounds checks.
// ----------------------------------------------------------------------------
#define SPAD 20
#define TILE_FLOATS (128 * SPAD)                  // 2560 per buffer per array
#define GEMM_SMEM_FLOATS (8 * TILE_FLOATS)        // 4 arrays x 2 buffers
#define GEMM_SMEM_BYTES  (GEMM_SMEM_FLOATS * sizeof(float))   // 81920

__global__ __launch_bounds__(256, 2)
void gemm_tc_nt_bias(const float* __restrict__ A, const float* __restrict__ B,
                     const float* __restrict__ bias, float* __restrict__ C,
                     int M, int N, int K) {
    extern __shared__ float sg[];
    float* AHs = sg;                      // [2][128][SPAD]
    float* ALs = sg + 2 * TILE_FLOATS;
    float* BHs = sg + 4 * TILE_FLOATS;
    float* BLs = sg + 6 * TILE_FLOATS;

    const int tid  = threadIdx.x;
    const int warp = tid >> 5;
    const int lane = tid & 31;
    const int g    = lane >> 2;    // 0..7
    const int t    = lane & 3;     // 0..3
    const int wm   = warp & 3;     // m offset wm*32
    const int wn   = warp >> 2;    // n offset wn*64

    const float* Ab = A + (size_t)blockIdx.y * 128 * K;
    const float* Bb = B + (size_t)blockIdx.x * 128 * K;

    // Staging slots: 2 float4 per thread for each of A,B per K-tile.
    const int row0 = tid >> 2,         k40 = (tid & 3) << 2;
    const int row1 = (tid + 256) >> 2; // same k40 for second slot
    const int soff0 = row0 * SPAD + k40;
    const int soff1 = row1 * SPAD + k40;

    float4 pa0, pa1, pb0, pb1;

    // Prologue: tile 0 -> split -> buffer 0.
    pa0 = *(const float4*)(Ab + (size_t)row0 * K + k40);
    pa1 = *(const float4*)(Ab + (size_t)row1 * K + k40);
    pb0 = *(const float4*)(Bb + (size_t)row0 * K + k40);
    pb1 = *(const float4*)(Bb + (size_t)row1 * K + k40);
    split_store4(pa0, AHs, ALs, soff0);
    split_store4(pa1, AHs, ALs, soff1);
    split_store4(pb0, BHs, BLs, soff0);
    split_store4(pb1, BHs, BLs, soff1);
    __syncthreads();

    float acc[2][8][4];
#pragma unroll
    for (int mt = 0; mt < 2; mt++)
#pragma unroll
        for (int nt = 0; nt < 8; nt++)
#pragma unroll
            for (int i = 0; i < 4; i++) acc[mt][nt][i] = 0.f;

    const int nk = K / 16;
    for (int tt = 0; tt < nk; tt++) {
        const int buf = tt & 1;
        const float* AH = AHs + buf * TILE_FLOATS;
        const float* AL = ALs + buf * TILE_FLOATS;
        const float* BH = BHs + buf * TILE_FLOATS;
        const float* BL = BLs + buf * TILE_FLOATS;

        // Prefetch raw tile t+1 into registers (overlaps MMA phase).
        if (tt + 1 < nk) {
            const int k0 = (tt + 1) * 16;
            pa0 = *(const float4*)(Ab + (size_t)row0 * K + k0 + k40);
            pa1 = *(const float4*)(Ab + (size_t)row1 * K + k0 + k40);
            pb0 = *(const float4*)(Bb + (size_t)row0 * K + k0 + k40);
            pb1 = *(const float4*)(Bb + (size_t)row1 * K + k0 + k40);
        }

#pragma unroll
        for (int s = 0; s < 2; s++) {           // two k8 steps per K-tile
            const int kb = s * 8;

            // --- hh: load ahi + bhi, 16 MMAs ---
            uint32_t ahi[2][4];
#pragma unroll
            for (int mt = 0; mt < 2; mt++) {
                const int rm = wm * 32 + mt * 16;
                ahi[mt][0] = __float_as_uint(AH[(rm + g)     * SPAD + kb + t]);
                ahi[mt][1] = __float_as_uint(AH[(rm + g + 8) * SPAD + kb + t]);
                ahi[mt][2] = __float_as_uint(AH[(rm + g)     * SPAD + kb + t + 4]);
                ahi[mt][3] = __float_as_uint(AH[(rm + g + 8) * SPAD + kb + t + 4]);
            }
            uint32_t bhi[8][2];
#pragma unroll
            for (int nt = 0; nt < 8; nt++) {
                const int nb = wn * 64 + nt * 8;
                bhi[nt][0] = __float_as_uint(BH[(nb + g) * SPAD + kb + t]);
                bhi[nt][1] = __float_as_uint(BH[(nb + g) * SPAD + kb + t + 4]);
            }
#pragma unroll
            for (int nt = 0; nt < 8; nt++)
#pragma unroll
                for (int mt = 0; mt < 2; mt++)
                    mma_tf32(acc[mt][nt], ahi[mt], bhi[nt]);

            // --- lh: load alo, 16 MMAs (bhi dies after this block) ---
            uint32_t alo[2][4];
#pragma unroll
            for (int mt = 0; mt < 2; mt++) {
                const int rm = wm * 32 + mt * 16;
                alo[mt][0] = __float_as_uint(AL[(rm + g)     * SPAD + kb + t]);
                alo[mt][1] = __float_as_uint(AL[(rm + g + 8) * SPAD + kb + t]);
                alo[mt][2] = __float_as_uint(AL[(rm + g)     * SPAD + kb + t + 4]);
                alo[mt][3] = __float_as_uint(AL[(rm + g + 8) * SPAD + kb + t + 4]);
            }
#pragma unroll
            for (int nt = 0; nt < 8; nt++)
#pragma unroll
                for (int mt = 0; mt < 2; mt++)
                    mma_tf32(acc[mt][nt], alo[mt], bhi[nt]);

            // --- hl: load blo, 16 MMAs (ahi still live) ---
            uint32_t blo[8][2];
#pragma unroll
            for (int nt = 0; nt < 8; nt++) {
                const int nb = wn * 64 + nt * 8;
                blo[nt][0] = __float_as_uint(BL[(nb + g) * SPAD + kb + t]);
                blo[nt][1] = __float_as_uint(BL[(nb + g) * SPAD + kb + t + 4]);
            }
#pragma unroll
            for (int nt = 0; nt < 8; nt++)
#pragma unroll
                for (int mt = 0; mt < 2; mt++)
                    mma_tf32(acc[mt][nt], ahi[mt], blo[nt]);
        }

        // Split + stage tile t+1 into alternate buffer; one barrier per tile.
        if (tt + 1 < nk) {
            const int nb = buf ^ 1;
            float* AHn = AHs + nb * TILE_FLOATS;
            float* ALn = ALs + nb * TILE_FLOATS;
            float* BHn = BHs + nb * TILE_FLOATS;
            float* BLn = BLs + nb * TILE_FLOATS;
            split_store4(pa0, AHn, ALn, soff0);
            split_store4(pa1, AHn, ALn, soff1);
            split_store4(pb0, BHn, BLn, soff0);
            split_store4(pb1, BHn, BLn, soff1);
            __syncthreads();
        }
    }

    // Epilogue: bias + store. c0:(g,2t) c1:(g,2t+1) c2:(g+8,2t) c3:(g+8,2t+1)
    const int rbase = blockIdx.y * 128 + wm * 32;
    const int cbase = blockIdx.x * 128 + wn * 64;
#pragma unroll
    for (int nt = 0; nt < 8; nt++) {
        const int cb = cbase + nt * 8 + 2 * t;
        const float2 bb = *(const float2*)&bias[cb];
#pragma unroll
        for (int mt = 0; mt < 2; mt++) {
            const int r0 = rbase + mt * 16 + g;
            float2 v0 = make_float2(acc[mt][nt][0] + bb.x, acc[mt][nt][1] + bb.y);
            float2 v1 = make_float2(acc[mt][nt][2] + bb.x, acc[mt][nt][3] + bb.y);
            *(float2*)(C + (size_t)r0 * N + cb)       = v0;
            *(float2*)(C + (size_t)(r0 + 8) * N + cb) = v1;
        }
    }
}

// ----------------------------------------------------------------------------
// Windowed attention: one CTA per (window, head).
// RoPE applied to q,k while loading into smem. 64x64 scores, softmax, PV.
// ----------------------------------------------------------------------------
#define QK_STRIDE (HD + 1)    // 81
#define P_STRIDE  (WIN + 1)   // 65
#define SM_Q 0
#define SM_K (WIN * QK_STRIDE)
#define SM_V (2 * WIN * QK_STRIDE)
#define SM_P (3 * WIN * QK_STRIDE)
#define ATTN_SMEM_FLOATS (3 * WIN * QK_STRIDE + WIN * P_STRIDE)

__global__ __launch_bounds__(256)
void attn_win(const float* __restrict__ cosT, const float* __restrict__ sinT) {
    extern __shared__ float sm[];
    float* sq = sm + SM_Q;
    float* sk = sm + SM_K;
    float* sv = sm + SM_V;
    float* sp = sm + SM_P;

    const int w   = blockIdx.x;
    const int h   = blockIdx.y;
    const int tid = threadIdx.x;

    const float* base = g_qkv + (size_t)w * WIN * QKV_N + h * HD;

    for (int idx = tid; idx < WIN * ROT; idx += 256) {
        int r = idx / ROT, j = idx - r * ROT;
        int t = w * WIN + r;
        float c = cosT[t * ROT + j];
        float s = sinT[t * ROT + j];
        const float* qp = base + (size_t)r * QKV_N;
        float q1 = qp[j], q2 = qp[j + ROT];
        sq[r * QK_STRIDE + j]       = q1 * c - q2 * s;
        sq[r * QK_STRIDE + j + ROT] = q2 * c + q1 * s;
        float k1 = qp[HIDDEN + j], k2 = qp[HIDDEN + j + ROT];
        sk[r * QK_STRIDE + j]       = k1 * c - k2 * s;
        sk[r * QK_STRIDE + j + ROT] = k2 * c + k1 * s;
    }
    for (int idx = tid; idx < WIN * HD; idx += 256) {
        int r = idx / HD, d = idx - r * HD;
        sv[r * QK_STRIDE + d] = base[(size_t)r * QKV_N + 2 * HIDDEN + d];
    }
    __syncthreads();

    {
        const int tx = tid & 15, ty = tid >> 4;
        float accs[4][4];
#pragma unroll
        for (int i = 0; i < 4; i++)
#pragma unroll
            for (int j = 0; j < 4; j++) accs[i][j] = 0.f;

        const float* qrow = sq + (ty * 4) * QK_STRIDE;
        const float* krow = sk + (tx * 4) * QK_STRIDE;
#pragma unroll 8
        for (int d = 0; d < HD; d++) {
            float qa[4], kb[4];
#pragma unroll
            for (int i = 0; i < 4; i++) qa[i] = qrow[i * QK_STRIDE + d];
#pragma unroll
            for (int j = 0; j < 4; j++) kb[j] = krow[j * QK_STRIDE + d];
#pragma unroll
            for (int i = 0; i < 4; i++)
#pragma unroll
                for (int j = 0; j < 4; j++)
                    accs[i][j] += qa[i] * kb[j];
        }
        const float scale = 0.11180339887498949f;   // 1/sqrt(80)
#pragma unroll
        for (int i = 0; i < 4; i++)
#pragma unroll
            for (int j = 0; j < 4; j++)
                sp[(ty * 4 + i) * P_STRIDE + tx * 4 + j] = accs[i][j] * scale;
    }
    __syncthreads();

    if (tid < WIN) {
        float* row = sp + tid * P_STRIDE;
        float m = row[0];
#pragma unroll 8
        for (int c = 1; c < WIN; c++) m = fmaxf(m, row[c]);
        float sum = 0.f;
#pragma unroll 8
        for (int c = 0; c < WIN; c++) {
            float e = __expf(row[c] - m);
            row[c] = e;
            sum += e;
        }
        float inv = 1.f / sum;
#pragma unroll 8
        for (int c = 0; c < WIN; c++) row[c] *= inv;
    }
    __syncthreads();

    {
        const int tx = tid & 15, ty = tid >> 4;
        float acco[4][5];
#pragma unroll
        for (int i = 0; i < 4; i++)
#pragma unroll
            for (int j = 0; j < 5; j++) acco[i][j] = 0.f;

#pragma unroll 4
        for (int c = 0; c < WIN; c++) {
            float pa[4], vb[5];
#pragma unroll
            for (int i = 0; i < 4; i++) pa[i] = sp[(ty * 4 + i) * P_STRIDE + c];
#pragma unroll
            for (int j = 0; j < 5; j++) vb[j] = sv[c * QK_STRIDE + tx * 5 + j];
#pragma unroll
            for (int i = 0; i < 4; i++)
#pragma unroll
                for (int j = 0; j < 5; j++)
                    acco[i][j] += pa[i] * vb[j];
        }
        float* outp = g_attn + (size_t)(w * WIN) * HIDDEN + h * HD;
#pragma unroll
        for (int i = 0; i < 4; i++)
#pragma unroll
            for (int j = 0; j < 5; j++)
                outp[(size_t)(ty * 4 + i) * HIDDEN + tx * 5 + j] = acco[i][j];
    }
}

// ----------------------------------------------------------------------------
// Launch: QKV GEMM -> windowed attention (RoPE fused) -> proj GEMM
// ----------------------------------------------------------------------------
extern "C" void kernel_launch(void* const* d_in, const int* in_sizes, int n_in,
                              void* d_out, int out_size) {
    const float* x      = (const float*)d_in[0];
    const float* cosT   = (const float*)d_in[1];
    const float* sinT   = (const float*)d_in[2];
    const float* qkv_w  = (const float*)d_in[3];
    const float* qkv_b  = (const float*)d_in[4];
    const float* proj_w = (const float*)d_in[5];
    const float* proj_b = (const float*)d_in[6];
    float* out = (float*)d_out;

    static float* qkv  = nullptr;
    static float* attn = nullptr;
    static bool   init = false;
    if (!init) {
        cudaGetSymbolAddress((void**)&qkv,  g_qkv);
        cudaGetSymbolAddress((void**)&attn, g_attn);
        cudaFuncSetAttribute(attn_win,
                             cudaFuncAttributeMaxDynamicSharedMemorySize,
                             (int)(ATTN_SMEM_FLOATS * sizeof(float)));
        cudaFuncSetAttribute(gemm_tc_nt_bias,
                             cudaFuncAttributeMaxDynamicSharedMemorySize,
                             (int)GEMM_SMEM_BYTES);
        init = true;
    }

    dim3 blk(256);

    dim3 g1(QKV_N / 128, S_TOT / 128);
    gemm_tc_nt_bias<<<g1, blk, GEMM_SMEM_BYTES>>>(x, qkv_w, qkv_b, qkv,
                                                  S_TOT, QKV_N, HIDDEN);

    attn_win<<<dim3(NWIN, NH), blk, ATTN_SMEM_FLOATS * sizeof(float)>>>(cosT, sinT);

    dim3 g2(HIDDEN / 128, S_TOT / 128);
    gemm_tc_nt_bias<<<g2, blk, GEMM_SMEM_BYTES>>>(attn, proj_w, proj_b, out,
                                                  S_TOT, HIDDEN, HIDDEN);
}